// round 5
// baseline (speedup 1.0000x reference)
#include <cuda_runtime.h>
#include <cstdint>

#define Bn 16
#define Tn 12
#define BT 192          // B*T
#define Nn 325
#define Dd 64
#define Hh 4
#define Ee 2600
#define ET (Ee + Nn)    // 2925 edges incl. self loops
#define NBT (Nn * BT)   // 62400 (n,bt) pairs

typedef unsigned long long ull;

// ---------------- packed f32x2 helpers (sm_103a FFMA2) ----------------
__device__ __forceinline__ void ffma2(ull& d, ull a, ull b) {
    asm("fma.rn.f32x2 %0, %1, %2, %0;" : "+l"(d) : "l"(a), "l"(b));
}
__device__ __forceinline__ ull pack2(float lo, float hi) {
    ull r; asm("mov.b64 %0, {%1,%2};" : "=l"(r) : "f"(lo), "f"(hi)); return r;
}
__device__ __forceinline__ void unpack2(float& lo, float& hi, ull v) {
    asm("mov.b64 {%0,%1}, %2;" : "=f"(lo), "=f"(hi) : "l"(v));
}

// ---------------- device scratch ----------------
__device__ __align__(16) float g_wsrc[Hh * Dd];
__device__ __align__(16) float g_wdst[Hh * Dd];
__device__ __align__(16) float g_Wcat[Hh * Dd * Dd];     // [k=h*64+d][f], pre-scaled 1/H
__device__ __align__(16) float g_asrc[NBT * Hh];
__device__ __align__(16) float g_adst[NBT * Hh];
__device__ int g_rowptr[Nn + 1];
__device__ int g_esrc[ET];

// ---------------- K0: setup (block 0 = CSR, block 1 = weight prep) ----------------
// edge_index may be int32 or int64 (JAX x64-config). Probe: int64 => every odd
// 32-bit word in the first 5200 words is 0 (values < 325).
__global__ void k_setup(const int* __restrict__ ew,
                        const float* __restrict__ W,
                        const float* __restrict__ att_src,
                        const float* __restrict__ att_dst) {
    int tid = threadIdx.x;
    int bd = blockDim.x;      // 1024
    if (blockIdx.x == 1) {
        if (tid < 256) {
            int h = tid >> 6, d = tid & 63;
            float s1 = 0.f, s2 = 0.f;
            #pragma unroll 8
            for (int f = 0; f < 64; f++) {
                float w = W[(d * Hh + h) * 64 + f];
                s1 += w * att_src[h * 64 + f];
                s2 += w * att_dst[h * 64 + f];
            }
            g_wsrc[tid] = s1;
            g_wdst[tid] = s2;
        }
        for (int i = tid; i < Hh * Dd * Dd; i += bd) {
            int k = i >> 6, f = i & 63;
            int hh = k >> 6, dd = k & 63;
            g_Wcat[i] = W[(dd * Hh + hh) * 64 + f] * 0.25f;  // 1/H folded
        }
        return;
    }
    // ---- CSR build, deterministic (sorted by original edge id) ----
    __shared__ int sdst[ET];
    __shared__ int ssrc[ET];
    __shared__ int sslot[ET];
    __shared__ int scnt[Nn + 1];
    __shared__ int scur[Nn];
    __shared__ int s_is32;
    if (tid == 0) s_is32 = 0;
    __syncthreads();
    for (int i = tid; i < Ee; i += bd)
        if (ew[2 * i + 1] != 0) s_is32 = 1;
    __syncthreads();
    int is32 = s_is32;
    for (int i = tid; i < ET; i += bd) {
        if (i < Ee) {
            if (is32) { ssrc[i] = ew[i];         sdst[i] = ew[Ee + i]; }
            else      { ssrc[i] = ew[2 * i];     sdst[i] = ew[2 * (Ee + i)]; }
        } else {
            ssrc[i] = i - Ee;
            sdst[i] = i - Ee;
        }
    }
    for (int i = tid; i <= Nn; i += bd) scnt[i] = 0;
    __syncthreads();
    for (int i = tid; i < ET; i += bd) atomicAdd(&scnt[sdst[i] + 1], 1);
    __syncthreads();
    if (tid == 0) {
        for (int i = 1; i <= Nn; i++) scnt[i] += scnt[i - 1];
    }
    __syncthreads();
    for (int i = tid; i <= Nn; i += bd) g_rowptr[i] = scnt[i];
    for (int i = tid; i < Nn; i += bd) scur[i] = scnt[i];
    __syncthreads();
    for (int e = tid; e < ET; e += bd) {
        int pos = atomicAdd(&scur[sdst[e]], 1);
        sslot[pos] = e;
    }
    __syncthreads();
    for (int n = tid; n < Nn; n += bd) {
        int a = scnt[n], b = scnt[n + 1];
        for (int i = a + 1; i < b; i++) {      // sort by edge id -> deterministic
            int v = sslot[i];
            int j = i - 1;
            while (j >= a && sslot[j] > v) { sslot[j + 1] = sslot[j]; j--; }
            sslot[j + 1] = v;
        }
        for (int p = a; p < b; p++) g_esrc[p] = ssrc[sslot[p]];
    }
}

// ---------------- K1: attention logits, warp per (n,bt) ----------------
__global__ __launch_bounds__(256) void k_alpha(const float* __restrict__ x) {
    __shared__ float sw[512];
    int tid = threadIdx.x;
    sw[tid] = g_wsrc[tid];
    sw[256 + tid] = g_wdst[tid];
    __syncthreads();
    int gid = blockIdx.x * 8 + (tid >> 5);
    int lane = tid & 31;
    int n = gid / BT, bt = gid % BT;
    float2 xv = ((const float2*)(x + ((size_t)bt * Nn + n) * 64))[lane];
    float p[8];
    #pragma unroll
    for (int h = 0; h < 4; h++) {
        p[h]     = xv.x * sw[h * 64 + 2 * lane]       + xv.y * sw[h * 64 + 2 * lane + 1];
        p[4 + h] = xv.x * sw[256 + h * 64 + 2 * lane] + xv.y * sw[256 + h * 64 + 2 * lane + 1];
    }
    #pragma unroll
    for (int o = 16; o; o >>= 1) {
        #pragma unroll
        for (int j = 0; j < 8; j++) p[j] += __shfl_xor_sync(0xffffffffu, p[j], o);
    }
    int base = gid * 4;
    if (lane < 4) g_asrc[base + lane] = p[lane];
    else if (lane < 8) g_adst[base + lane - 4] = p[lane];
}

// ---------------- K2: fused aggregation + GEMM + LayerNorm ----------------
// Block = one node n, 96 bt values. Phase 1: 8 warps x 12 rows aggregate in
// input space into shared As[256][98] (k-major). Phase 2: 96x64 GEMM with
// FFMA2, B chunk-duplicated {w,w}. Epilogue: bias + residual + LayerNorm.
#define ASTR 98
#define SM_FLOATS (25088 + 2048 + 256)   // As + s_cf(8KB) + s_src(1KB)

__device__ __forceinline__ float lrelu(float v) { return v >= 0.f ? v : 0.2f * v; }

__global__ __launch_bounds__(256, 2) void k_fused(const float* __restrict__ x,
                                                  const float* __restrict__ bias,
                                                  const float* __restrict__ gamma,
                                                  const float* __restrict__ beta,
                                                  float* __restrict__ out) {
    extern __shared__ float sm[];
    float* As  = sm;                          // [256][98] = 25088 floats
    ull*  s_cf  = (ull*)(sm + 25088);         // [8][32][4] ull = 8192B (phase1)
    int*  s_src = (int*)(sm + 25088 + 2048);  // [8][32] int (phase1)
    ull*  Bsd   = (ull*)(sm + 25088);         // [16][64] ull = 8192B (phase2 alias)

    const unsigned full = 0xffffffffu;
    int tid = threadIdx.x, w = tid >> 5, lane = tid & 31;
    int b = blockIdx.x;
    int n = b >> 1, bt0 = (b & 1) * 96;
    int rs = g_rowptr[n], re = g_rowptr[n + 1];
    int deg = re - rs;

    // ----- phase 1: aggregate 12 rows per warp into As (k-major) -----
    for (int rr = 0; rr < 12; rr++) {
        int row = w * 12 + rr;
        int bt = bt0 + row;
        int gid = n * BT + bt;
        float4 adv = *(const float4*)(g_adst + gid * 4);
        float smh[4] = {0.f, 0.f, 0.f, 0.f};
        float c0[4] = {0.f, 0.f, 0.f, 0.f};
        int s0 = 0;
        int e0 = rs + lane;
        for (int e = e0; e < re; e += 32) {
            int s = g_esrc[e];
            float4 av = *(const float4*)(g_asrc + (s * BT + bt) * 4);
            float v0 = __expf(lrelu(av.x + adv.x));
            float v1 = __expf(lrelu(av.y + adv.y));
            float v2 = __expf(lrelu(av.z + adv.z));
            float v3 = __expf(lrelu(av.w + adv.w));
            smh[0] += v0; smh[1] += v1; smh[2] += v2; smh[3] += v3;
            if (e == e0) { s0 = s; c0[0] = v0; c0[1] = v1; c0[2] = v2; c0[3] = v3; }
        }
        #pragma unroll
        for (int o = 16; o; o >>= 1) {
            #pragma unroll
            for (int h = 0; h < 4; h++) smh[h] += __shfl_xor_sync(full, smh[h], o);
        }
        float inv[4];
        #pragma unroll
        for (int h = 0; h < 4; h++) inv[h] = 1.f / (smh[h] + 1e-16f);
        if (lane < deg) {
            s_src[w * 32 + lane] = s0;
            #pragma unroll
            for (int h = 0; h < 4; h++) {
                float c = c0[h] * inv[h];
                s_cf[(w * 32 + lane) * 4 + h] = pack2(c, c);
            }
        }
        __syncwarp();

        ull acc0 = 0, acc1 = 0, acc2 = 0, acc3 = 0;
        const float* xb = x + (size_t)bt * (Nn * 64);
        int jm = deg < 32 ? deg : 32;
        for (int j = 0; j < jm; j++) {
            int src = s_src[w * 32 + j];
            ulonglong2 cA = *(const ulonglong2*)&s_cf[(w * 32 + j) * 4];
            ulonglong2 cB = *(const ulonglong2*)&s_cf[(w * 32 + j) * 4 + 2];
            ull xv = *(const ull*)(xb + src * 64 + 2 * lane);
            ffma2(acc0, xv, cA.x);
            ffma2(acc1, xv, cA.y);
            ffma2(acc2, xv, cB.x);
            ffma2(acc3, xv, cB.y);
        }
        for (int j = 32; j < deg; j++) {          // rare: degree > 32
            int src = g_esrc[rs + j];
            float4 av = *(const float4*)(g_asrc + (src * BT + bt) * 4);
            float cc0 = __expf(lrelu(av.x + adv.x)) * inv[0];
            float cc1 = __expf(lrelu(av.y + adv.y)) * inv[1];
            float cc2 = __expf(lrelu(av.z + adv.z)) * inv[2];
            float cc3 = __expf(lrelu(av.w + adv.w)) * inv[3];
            ull xv = *(const ull*)(xb + src * 64 + 2 * lane);
            ffma2(acc0, xv, pack2(cc0, cc0));
            ffma2(acc1, xv, pack2(cc1, cc1));
            ffma2(acc2, xv, pack2(cc2, cc2));
            ffma2(acc3, xv, pack2(cc3, cc3));
        }
        // store k-major: k = h*64 + 2*lane (+1)
        float lo, hi;
        unpack2(lo, hi, acc0);
        As[(0 * 64 + 2 * lane) * ASTR + row] = lo;
        As[(0 * 64 + 2 * lane + 1) * ASTR + row] = hi;
        unpack2(lo, hi, acc1);
        As[(1 * 64 + 2 * lane) * ASTR + row] = lo;
        As[(1 * 64 + 2 * lane + 1) * ASTR + row] = hi;
        unpack2(lo, hi, acc2);
        As[(2 * 64 + 2 * lane) * ASTR + row] = lo;
        As[(2 * 64 + 2 * lane + 1) * ASTR + row] = hi;
        unpack2(lo, hi, acc3);
        As[(3 * 64 + 2 * lane) * ASTR + row] = lo;
        As[(3 * 64 + 2 * lane + 1) * ASTR + row] = hi;
        __syncwarp();
    }
    __syncthreads();

    // ----- phase 2: GEMM 96x64 = As[256][96rows] x Wcat[256][64] -----
    int tcol = tid & 15, trowg = tid >> 4;       // 16 colgroups x 16 rowpair-groups
    ull acc[3][4];
    #pragma unroll
    for (int i = 0; i < 3; i++)
        #pragma unroll
        for (int j = 0; j < 4; j++) acc[i][j] = 0ull;

    for (int kc = 0; kc < 256; kc += 16) {
        {   // prep Bsd chunk: [kk][f] = {w,w}
            int kk = tid >> 4, f0 = (tid & 15) * 4;
            float4 v = *(const float4*)(g_Wcat + (size_t)(kc + kk) * 64 + f0);
            Bsd[kk * 64 + f0 + 0] = pack2(v.x, v.x);
            Bsd[kk * 64 + f0 + 1] = pack2(v.y, v.y);
            Bsd[kk * 64 + f0 + 2] = pack2(v.z, v.z);
            Bsd[kk * 64 + f0 + 3] = pack2(v.w, v.w);
        }
        __syncthreads();
        #pragma unroll
        for (int kk = 0; kk < 16; kk++) {
            const float* ak = As + (size_t)(kc + kk) * ASTR + 2 * trowg;
            ull a0 = *(const ull*)(ak);
            ull a1 = *(const ull*)(ak + 32);
            ull a2 = *(const ull*)(ak + 64);
            ulonglong2 b01 = *(const ulonglong2*)&Bsd[kk * 64 + tcol * 4];
            ulonglong2 b23 = *(const ulonglong2*)&Bsd[kk * 64 + tcol * 4 + 2];
            ffma2(acc[0][0], a0, b01.x); ffma2(acc[0][1], a0, b01.y);
            ffma2(acc[0][2], a0, b23.x); ffma2(acc[0][3], a0, b23.y);
            ffma2(acc[1][0], a1, b01.x); ffma2(acc[1][1], a1, b01.y);
            ffma2(acc[1][2], a1, b23.x); ffma2(acc[1][3], a1, b23.y);
            ffma2(acc[2][0], a2, b01.x); ffma2(acc[2][1], a2, b01.y);
            ffma2(acc[2][2], a2, b23.x); ffma2(acc[2][3], a2, b23.y);
        }
        __syncthreads();
    }

    // ----- stage C into shared (alias As) -----
    float* CS = sm;                               // 96x64 floats
    #pragma unroll
    for (int i = 0; i < 3; i++) {
        int pr = trowg + 16 * i;
        float l0, h0, l1, h1, l2, h2, l3, h3;
        unpack2(l0, h0, acc[i][0]);
        unpack2(l1, h1, acc[i][1]);
        unpack2(l2, h2, acc[i][2]);
        unpack2(l3, h3, acc[i][3]);
        *(float4*)&CS[(2 * pr) * 64 + tcol * 4]     = make_float4(l0, l1, l2, l3);
        *(float4*)&CS[(2 * pr + 1) * 64 + tcol * 4] = make_float4(h0, h1, h2, h3);
    }
    __syncthreads();

    // ----- epilogue: bias + residual + LayerNorm, warp per row -----
    float2 bi = ((const float2*)bias)[lane];
    float2 ga = ((const float2*)gamma)[lane];
    float2 be = ((const float2*)beta)[lane];
    #pragma unroll
    for (int it = 0; it < 12; it++) {
        int row = w * 12 + it;
        int bt = bt0 + row;
        size_t xo = ((size_t)bt * Nn + n) * 64;
        float2 c = *(const float2*)(CS + row * 64 + lane * 2);
        float2 xv = *(const float2*)(x + xo + lane * 2);
        float yx = xv.x + c.x + bi.x;
        float yy = xv.y + c.y + bi.y;
        float s = yx + yy;
        float s2 = yx * yx + yy * yy;
        #pragma unroll
        for (int o = 16; o; o >>= 1) {
            s += __shfl_xor_sync(full, s, o);
            s2 += __shfl_xor_sync(full, s2, o);
        }
        float mu = s * (1.f / 64.f);
        float var = s2 * (1.f / 64.f) - mu * mu;
        float rstd = rsqrtf(var + 1e-5f);
        float2 o2;
        o2.x = (yx - mu) * rstd * ga.x + be.x;
        o2.y = (yy - mu) * rstd * ga.y + be.y;
        *(float2*)(out + xo + lane * 2) = o2;
    }
}

// ---------------- launcher ----------------
extern "C" void kernel_launch(void* const* d_in, const int* in_sizes, int n_in,
                              void* d_out, int out_size) {
    const float* x        = (const float*)d_in[0];
    const float* W        = (const float*)d_in[1];
    const float* att_src  = (const float*)d_in[2];
    const float* att_dst  = (const float*)d_in[3];
    const float* bias     = (const float*)d_in[4];
    const float* gamma    = (const float*)d_in[5];
    const float* beta     = (const float*)d_in[6];
    const int*   edge     = (const int*)d_in[7];
    float* out = (float*)d_out;

    static bool attr_set = false;
    if (!attr_set) {
        cudaFuncSetAttribute(k_fused, cudaFuncAttributeMaxDynamicSharedMemorySize,
                             SM_FLOATS * 4);
        attr_set = true;
    }
    k_setup<<<2, 1024>>>(edge, W, att_src, att_dst);
    k_alpha<<<NBT / 8, 256>>>(x);
    k_fused<<<Nn * 2, 256, SM_FLOATS * 4>>>(x, bias, gamma, beta, out);
}